// round 14
// baseline (speedup 1.0000x reference)
#include <cuda_runtime.h>
#include <cuda_bf16.h>
#include <math.h>
#include <stdint.h>

#define BN 32
#define CN 1024
#define QN 128
#define DN 768
#define ODN 3072

// ---------------- smem layout (32-bit word offsets) ---------------------------
// GEMM1: 3 stages x 9216 words [0, 27648): per stage ctx 128x36 + A 128x36
// GEMM2/epilogue (aliased): P bf16 [0,8704), QT bf16 64x68 [8704,13056),
//                           O stage f32 128x68 [17408,26112)
// masks+SRED live in stage-2 footprint, written AFTER GEMM1:
#define P_F     0
#define QTBF_F  8704
#define OST_F   17408
#define SXQ_F   26112
#define SQM_F   26240
#define SCM_F   26368
#define SRED_F  26496   // 512 f
#define SMEM_FLOATS 27648
#define SMEM_BYTES (SMEM_FLOATS*4)

// ---------------- scratch ----------------------------------------------------
__device__ float g_A[(size_t)BN*QN*DN];              // wc + query*wqc
__device__ __nv_bfloat16 g_QTbf[(size_t)BN*DN*QN];   // query^T in bf16 [b][d][q]
__device__ float g_xq[BN*QN];
__device__ float g_m[BN*CN];
__device__ float g_qp[(size_t)BN*8*DN];              // q2c partials

__device__ __forceinline__ float finf() { return __int_as_float(0x7f800000); }

__device__ __forceinline__ uint32_t s2u(const void* p) {
    uint32_t a;
    asm("{ .reg .u64 t; cvta.to.shared.u64 t, %1; cvt.u32.u64 %0, t; }" : "=r"(a) : "l"(p));
    return a;
}
__device__ __forceinline__ void cpa16(uint32_t dst, const void* src) {
    asm volatile("cp.async.cg.shared.global [%0], [%1], 16;" :: "r"(dst), "l"(src));
}
#define CP_COMMIT() asm volatile("cp.async.commit_group;" ::: "memory")
#define CP_WAIT0()  asm volatile("cp.async.wait_group 0;" ::: "memory")
#define CP_WAIT1()  asm volatile("cp.async.wait_group 1;" ::: "memory")

// m16n8k8 tf32 mma, D += A*B (fp32 accum). Raw fp32 bits as tf32 operands.
__device__ __forceinline__ void mma8(float* d, const uint32_t* a, const uint32_t* b) {
    asm volatile("mma.sync.aligned.m16n8k8.row.col.f32.tf32.tf32.f32 "
        "{%0,%1,%2,%3}, {%4,%5,%6,%7}, {%8,%9}, {%0,%1,%2,%3};"
        : "+f"(d[0]), "+f"(d[1]), "+f"(d[2]), "+f"(d[3])
        : "r"(a[0]), "r"(a[1]), "r"(a[2]), "r"(a[3]), "r"(b[0]), "r"(b[1]));
}
// m16n8k16 bf16 mma, D += A*B (fp32 accum).
__device__ __forceinline__ void mma16(float* d, const uint32_t* a, const uint32_t* b) {
    asm volatile("mma.sync.aligned.m16n8k16.row.col.f32.bf16.bf16.f32 "
        "{%0,%1,%2,%3}, {%4,%5,%6,%7}, {%8,%9}, {%0,%1,%2,%3};"
        : "+f"(d[0]), "+f"(d[1]), "+f"(d[2]), "+f"(d[3])
        : "r"(a[0]), "r"(a[1]), "r"(a[2]), "r"(a[3]), "r"(b[0]), "r"(b[1]));
}
#define LDSM4(d0,d1,d2,d3,a) \
    asm volatile("ldmatrix.sync.aligned.m8n8.x4.shared.b16 {%0,%1,%2,%3}, [%4];" \
        : "=r"(d0), "=r"(d1), "=r"(d2), "=r"(d3) : "r"(a))

// ---------------- kernel 1: A = wc + query*wqc ; xq = query . wq -------------
__global__ void prep_kernel(const float* __restrict__ query,
                            const float* __restrict__ wq,
                            const float* __restrict__ wc,
                            const float* __restrict__ wqc) {
    int row = blockIdx.x;
    int t = threadIdx.x;           // 0..191
    float4 q4  = reinterpret_cast<const float4*>(query)[(size_t)row*192 + t];
    float4 wq4 = reinterpret_cast<const float4*>(wq)[t];
    float4 wc4 = reinterpret_cast<const float4*>(wc)[t];
    float4 wqc4= reinterpret_cast<const float4*>(wqc)[t];
    float4 a4;
    a4.x = wc4.x + q4.x*wqc4.x;
    a4.y = wc4.y + q4.y*wqc4.y;
    a4.z = wc4.z + q4.z*wqc4.z;
    a4.w = wc4.w + q4.w*wqc4.w;
    reinterpret_cast<float4*>(g_A)[(size_t)row*192 + t] = a4;
    float dot = q4.x*wq4.x + q4.y*wq4.y + q4.z*wq4.z + q4.w*wq4.w;
    #pragma unroll
    for (int o=16;o;o>>=1) dot += __shfl_xor_sync(0xffffffffu, dot, o);
    __shared__ float red[6];
    if ((t&31)==0) red[t>>5]=dot;
    __syncthreads();
    if (t==0) g_xq[row] = red[0]+red[1]+red[2]+red[3]+red[4]+red[5];
}

// ---------------- kernel 1b: QTbf[b][d][q] = bf16(query[b][q][d]) ------------
__global__ void qtrans_kernel(const float* __restrict__ query) {
    __shared__ float tile[32][33];
    int b = blockIdx.z, dt = blockIdx.x, qt = blockIdx.y;
    int tx = threadIdx.x, ty = threadIdx.y;   // (32,8)
    const float* qb = query + (size_t)b*QN*DN;
    #pragma unroll
    for (int i=0;i<32;i+=8)
        tile[ty+i][tx] = qb[(size_t)(qt*32+ty+i)*DN + dt*32+tx];
    __syncthreads();
    __nv_bfloat16* QTb = g_QTbf + (size_t)b*DN*QN;
    #pragma unroll
    for (int i=0;i<32;i+=8)
        QTb[(size_t)(dt*32+ty+i)*QN + qt*32+tx] = __float2bfloat16_rn(tile[tx][ty+i]);
}

// ---------------- probe: keeps main_kernel at launch slot #4 for ncu ---------
__global__ void probe_kernel() {
    if (threadIdx.x == 0 && blockIdx.x == 0) g_qp[0] = 0.f;  // overwritten by q2c later
}

// ---------------- kernel 2: main fused mma.sync kernel -----------------------
// grid (8, 32), 512 threads (16 warps in 4x4). smem 110592 B, 2 CTAs/SM.
__device__ __forceinline__ void load_g1(const float* ctxB, const float* AqB,
                                        uint32_t sb, int kt, int st, int tid) {
    int k0 = kt*32;
    #pragma unroll
    for (int p=0;p<2;p++) {
        int idx = tid + p*512;                 // 0..1023
        int row = idx >> 3, seg = idx & 7;
        uint32_t off = (uint32_t)(st*9216 + row*36 + seg*4)*4;
        cpa16(sb + off, ctxB + (size_t)row*DN + k0 + seg*4);
    }
    #pragma unroll
    for (int p=0;p<2;p++) {
        int idx = tid + p*512;
        int row = idx >> 3, seg = idx & 7;
        uint32_t off = (uint32_t)(st*9216 + 4608 + row*36 + seg*4)*4;
        cpa16(sb + off, AqB + (size_t)row*DN + k0 + seg*4);
    }
}

__global__ __launch_bounds__(512, 2)
void main_kernel(const float* __restrict__ ctx,
                 const int* __restrict__ cmask,
                 const int* __restrict__ qmask,
                 float* __restrict__ out) {
    extern __shared__ float smf[];
    uint32_t* smw = (uint32_t*)smf;
    const uint32_t sb = s2u(smf);
    const int tid = threadIdx.x;
    const int wid = tid >> 5, lane = tid & 31;
    const int g = lane >> 2, t = lane & 3;
    const int wm = wid >> 2, wn = wid & 3;   // 4 x 4 warp grid
    const int b = blockIdx.y;
    const int cbase = blockIdx.x << 7;
    const float* ctxB = ctx + ((size_t)(b*CN + cbase))*DN;
    const float* AqB  = g_A + (size_t)b*QN*DN;
    const __nv_bfloat16* QTb = g_QTbf + (size_t)b*DN*QN;

    const int rr = lane & 7, sel = lane >> 3;

    float acc[2][4][4];
    #pragma unroll
    for (int mt=0;mt<2;mt++)
      #pragma unroll
      for (int nt=0;nt<4;nt++)
        #pragma unroll
        for (int r=0;r<4;r++) acc[mt][nt][r]=0.f;

    // GEMM1 ldmatrix base offsets (bytes, relative to stage base).
    // tf32-as-b16 trick: one 8x8 b16 tile == 8 rows x 4 tf32 cols; lane l
    // receives (row l>>2, word l&3) == the (g,t) tf32 fragment mapping.
    uint32_t aOff[2], bOff[2];
    #pragma unroll
    for (int mt=0;mt<2;mt++)
        aOff[mt] = (uint32_t)(((wm*32 + mt*16 + (sel&1)*8 + rr)*36 + (sel>>1)*4)*4);
    #pragma unroll
    for (int j=0;j<2;j++)
        bOff[j]  = (uint32_t)((4608 + (wn*32 + j*16 + (sel&1)*8 + rr)*36 + (sel>>1)*4)*4);

    // -------- GEMM1: S = ctx @ A^T, tf32, 24 K-chunks of 32, 3 stages --------
    load_g1(ctxB, AqB, sb, 0, 0, tid); CP_COMMIT();
    load_g1(ctxB, AqB, sb, 1, 1, tid); CP_COMMIT();
    for (int kt = 0; kt < 24; kt++) {
        CP_WAIT1();                       // stage kt data arrived
        __syncthreads();                  // stage (kt+2)%3 readers (iter kt-1) done
        if (kt + 2 < 24) load_g1(ctxB, AqB, sb, kt+2, (kt+2)%3, tid);
        CP_COMMIT();
        const uint32_t stb = sb + (uint32_t)((kt%3)*9216)*4;
        #pragma unroll
        for (int k8=0;k8<4;k8++) {
            uint32_t a[2][4], bb[4][2];
            LDSM4(a[0][0], a[0][1], a[0][2], a[0][3], stb + aOff[0] + k8*32);
            LDSM4(a[1][0], a[1][1], a[1][2], a[1][3], stb + aOff[1] + k8*32);
            LDSM4(bb[0][0], bb[1][0], bb[0][1], bb[1][1], stb + bOff[0] + k8*32);
            LDSM4(bb[2][0], bb[3][0], bb[2][1], bb[3][1], stb + bOff[1] + k8*32);
            #pragma unroll
            for (int mt=0;mt<2;mt++)
              #pragma unroll
              for (int nt=0;nt<4;nt++)
                mma8(acc[mt][nt], a[mt], bb[nt]);
        }
    }
    __syncthreads();   // all compute done; stage buffers reusable

    // prefetch QT chunk 0 (overlaps the whole softmax epilogue)
    #pragma unroll
    for (int p=0;p<2;p++) {
        int idx = tid + p*512;               // 1024 chunks: 64 rows x 16
        int r = idx >> 4, c = idx & 15;
        cpa16(sb + (uint32_t)(QTBF_F + r*68 + c*4)*4, QTb + (size_t)r*QN + c*8);
    }
    CP_COMMIT();

    // -------- load masks/xq (into stage-2 footprint) -------------------------
    if (tid < 128) {
        smf[SXQ_F + tid] = g_xq[b*QN + tid];
        smf[SQM_F + tid] = (qmask[b*QN + tid] == 1) ? 1.0f : -finf();
        smf[SCM_F + tid] = (cmask[b*CN + cbase + tid] == 1) ? 1.0f : -finf();
    }
    __syncthreads();

    // -------- bias + masks + row softmax over q ------------------------------
    float cm[2][2];
    #pragma unroll
    for (int mt=0;mt<2;mt++) {
        int r0 = wm*32 + mt*16 + g;
        cm[mt][0] = smf[SCM_F + r0];
        cm[mt][1] = smf[SCM_F + r0 + 8];
    }
    float rowmax[2][2];
    #pragma unroll
    for (int mt=0;mt<2;mt++) { rowmax[mt][0] = -finf(); rowmax[mt][1] = -finf(); }
    #pragma unroll
    for (int mt=0;mt<2;mt++)
      #pragma unroll
      for (int nt=0;nt<4;nt++)
        #pragma unroll
        for (int r=0;r<4;r++) {
            int h = r>>1, e = r&1;
            int c0 = wn*32 + nt*8 + 2*t + e;
            float v = (acc[mt][nt][r] + smf[SXQ_F + c0]) * cm[mt][h] * smf[SQM_F + c0];
            if (v == finf()) v = -finf();
            acc[mt][nt][r] = v;
            rowmax[mt][h] = fmaxf(rowmax[mt][h], v);
        }
    #pragma unroll
    for (int mt=0;mt<2;mt++)
      #pragma unroll
      for (int h=0;h<2;h++) {
        float m = rowmax[mt][h];
        m = fmaxf(m, __shfl_xor_sync(0xffffffffu, m, 1));
        m = fmaxf(m, __shfl_xor_sync(0xffffffffu, m, 2));
        if (t == 0) smf[SRED_F + (wm*32 + mt*16 + g + 8*h)*4 + wn] = m;
      }
    __syncthreads();
    float mx[2][2];
    #pragma unroll
    for (int mt=0;mt<2;mt++)
      #pragma unroll
      for (int h=0;h<2;h++) {
        int row = wm*32 + mt*16 + g + 8*h;
        float4 mm = *(const float4*)&smf[SRED_F + row*4];
        float m = fmaxf(fmaxf(mm.x, mm.y), fmaxf(mm.z, mm.w));
        mx[mt][h] = m;
        if (wn == 0 && t == 0) g_m[b*CN + cbase + row] = m;
      }
    float rowsum[2][2];
    #pragma unroll
    for (int mt=0;mt<2;mt++) { rowsum[mt][0] = 0.f; rowsum[mt][1] = 0.f; }
    #pragma unroll
    for (int mt=0;mt<2;mt++)
      #pragma unroll
      for (int nt=0;nt<4;nt++)
        #pragma unroll
        for (int r=0;r<4;r++) {
            int h = r>>1;
            float e = expf(acc[mt][nt][r] - mx[mt][h]);
            acc[mt][nt][r] = e;
            rowsum[mt][h] += e;
        }
    __syncthreads();
    #pragma unroll
    for (int mt=0;mt<2;mt++)
      #pragma unroll
      for (int h=0;h<2;h++) {
        float s = rowsum[mt][h];
        s += __shfl_xor_sync(0xffffffffu, s, 1);
        s += __shfl_xor_sync(0xffffffffu, s, 2);
        if (t == 0) smf[SRED_F + (wm*32 + mt*16 + g + 8*h)*4 + wn] = s;
      }
    __syncthreads();
    // normalize + pack P to bf16x2 words (stride 68, conflict-free)
    #pragma unroll
    for (int mt=0;mt<2;mt++)
      #pragma unroll
      for (int h=0;h<2;h++) {
        int row = wm*32 + mt*16 + g + 8*h;
        float4 ss = *(const float4*)&smf[SRED_F + row*4];
        float inv = 1.0f / (ss.x + ss.y + ss.z + ss.w);
        #pragma unroll
        for (int nt=0;nt<4;nt++) {
            __nv_bfloat162 pv = __floats2bfloat162_rn(acc[mt][nt][h*2+0]*inv,
                                                      acc[mt][nt][h*2+1]*inv);
            smw[P_F + row*68 + wn*16 + nt*4 + t] = *(uint32_t*)&pv;
        }
      }
    __syncthreads();

    // -------- GEMM2: per 64-d chunk O = P @ QT^T (bf16, ldmatrix, pipelined) -
    const uint32_t aB0 = sb + (uint32_t)(P_F + (wm*32 + (sel&1)*8 + rr)*68 + (sel>>1)*4)*4;
    const uint32_t aB1 = aB0 + 16*68*4;
    const uint32_t bB  = sb + (uint32_t)(QTBF_F + (wn*16 + (sel>>1)*8 + rr)*68 + (sel&1)*4)*4;

    for (int dc = 0; dc < 12; dc++) {
        const int dbase = dc*64;
        CP_WAIT0();                       // QT(dc) arrived
        __syncthreads();
        float o2[2][2][4];
        #pragma unroll
        for (int mt=0;mt<2;mt++)
          #pragma unroll
          for (int nt=0;nt<2;nt++)
            #pragma unroll
            for (int r=0;r<4;r++) o2[mt][nt][r]=0.f;
        #pragma unroll
        for (int kk=0;kk<8;kk++) {
            uint32_t a[2][4], bb[2][2];
            LDSM4(a[0][0], a[0][1], a[0][2], a[0][3], aB0 + kk*32);
            LDSM4(a[1][0], a[1][1], a[1][2], a[1][3], aB1 + kk*32);
            LDSM4(bb[0][0], bb[0][1], bb[1][0], bb[1][1], bB + kk*32);
            #pragma unroll
            for (int mt=0;mt<2;mt++)
              #pragma unroll
              for (int nt=0;nt<2;nt++)
                mma16(o2[mt][nt], a[mt], bb[nt]);
        }
        __syncthreads();                  // QT(dc) reads done; buffer reusable
        if (dc < 11) {                    // prefetch QT(dc+1) under staging+stores
            const int dn = (dc+1)*64;
            #pragma unroll
            for (int p=0;p<2;p++) {
                int idx = tid + p*512;
                int r = idx >> 4, c = idx & 15;
                cpa16(sb + (uint32_t)(QTBF_F + r*68 + c*4)*4,
                      QTb + (size_t)(dn + r)*QN + c*8);
            }
            CP_COMMIT();
        }
        // stage O (f32, stride 68), then coalesced float4 stores
        #pragma unroll
        for (int mt=0;mt<2;mt++)
          #pragma unroll
          for (int h=0;h<2;h++) {
            int row = wm*32 + mt*16 + g + 8*h;
            #pragma unroll
            for (int nt=0;nt<2;nt++) {
                float2 ov = make_float2(o2[mt][nt][h*2+0], o2[mt][nt][h*2+1]);
                *(float2*)&smf[OST_F + row*68 + wn*16 + nt*8 + 2*t] = ov;
            }
          }
        __syncthreads();
        #pragma unroll
        for (int p=0;p<4;p++) {
            int row = p*32 + (tid>>4);
            int c4 = (tid&15)*4;
            float4 ov = *(const float4*)&smf[OST_F + row*68 + c4];
            size_t orow = (size_t)(b*CN + cbase + row);
            float4 cv = *(const float4*)(ctx + orow*DN + dbase + c4);
            float* op = out + orow*ODN + dbase + c4;
            __stcs((float4*)(op), cv);
            __stcs((float4*)(op + DN), ov);
            __stcs((float4*)(op + 2*DN),
                   make_float4(cv.x*ov.x, cv.y*ov.y, cv.z*ov.z, cv.w*ov.w));
        }
        __syncthreads();   // OST reads done before next iteration's staging
    }
}

// ---------------- kernel 4: q2c partials (softmax weights inlined) -----------
// grid (6, 32, 8), 256 threads.
__global__ void q2c_kernel(const float* __restrict__ ctx) {
    int b = blockIdx.y;
    int dbase = blockIdx.x << 7;
    int cz = blockIdx.z;
    int t = threadIdx.x;

    // inline softmax over c of g_m[b] (same op order as the old softc_kernel)
    __shared__ float smx[8], ssm[8], sw[128];
    float v[4]; float mxv = -finf();
    #pragma unroll
    for (int i=0;i<4;i++) { v[i] = g_m[b*CN + t + i*256]; mxv = fmaxf(mxv, v[i]); }
    #pragma unroll
    for (int o=16;o;o>>=1) mxv = fmaxf(mxv, __shfl_xor_sync(0xffffffffu, mxv, o));
    if ((t&31)==0) smx[t>>5]=mxv;
    __syncthreads();
    float bm = smx[0];
    #pragma unroll
    for (int i=1;i<8;i++) bm = fmaxf(bm, smx[i]);
    float s = 0.f;
    #pragma unroll
    for (int i=0;i<4;i++) { float e = expf(v[i]-bm); s+=e; }
    #pragma unroll
    for (int o=16;o;o>>=1) s += __shfl_xor_sync(0xffffffffu, s, o);
    if ((t&31)==0) ssm[t>>5]=s;
    __syncthreads();
    float tot = ssm[0]+ssm[1]+ssm[2]+ssm[3]+ssm[4]+ssm[5]+ssm[6]+ssm[7];
    float inv = 1.0f / tot;
    if (t < 128)
        sw[t] = expf(g_m[b*CN + cz*128 + t] - bm) * inv;
    __syncthreads();

    int col = t & 127;
    int half = t >> 7;
    const float* cp = ctx + ((size_t)(b*CN) + cz*128 + half*64)*DN + dbase + col;
    const float* wp = sw + half*64;
    float a0=0.f,a1=0.f,a2=0.f,a3=0.f;
    for (int c=0;c<64;c+=4) {
        a0 += wp[c+0]*cp[(size_t)(c+0)*DN];
        a1 += wp[c+1]*cp[(size_t)(c+1)*DN];
        a2 += wp[c+2]*cp[(size_t)(c+2)*DN];
        a3 += wp[c+3]*cp[(size_t)(c+3)*DN];
    }
    float acc = (a0+a1)+(a2+a3);
    __shared__ float sred[128];
    if (half) sred[col] = acc;
    __syncthreads();
    if (!half) g_qp[((size_t)b*8 + cz)*DN + dbase + col] = acc + sred[col];
}

// ---------------- kernel 5: part4 = ctx * q2c (8-partial reduce inlined) -----
__global__ void part4_kernel(const float* __restrict__ ctx, float* __restrict__ out) {
    int i4 = blockIdx.x*blockDim.x + threadIdx.x;
    int bc = i4 / 192;
    int d4 = i4 - bc*192;
    int b = bc >> 10;
    float4 cv = reinterpret_cast<const float4*>(ctx)[(size_t)bc*192 + d4];
    float4 qv = make_float4(0.f, 0.f, 0.f, 0.f);
    #pragma unroll
    for (int z=0;z<8;z++) {
        float4 p = reinterpret_cast<const float4*>(g_qp)[((size_t)b*8 + z)*192 + d4];
        qv.x += p.x; qv.y += p.y; qv.z += p.z; qv.w += p.w;
    }
    float4 rr = make_float4(cv.x*qv.x, cv.y*qv.y, cv.z*qv.z, cv.w*qv.w);
    __stcs(&reinterpret_cast<float4*>(out)[(size_t)bc*768 + 576 + d4], rr);
}

// ---------------- launch -----------------------------------------------------
extern "C" void kernel_launch(void* const* d_in, const int* in_sizes, int n_in,
                              void* d_out, int out_size) {
    const float* ctx   = (const float*)d_in[0];
    const int*   cmask = (const int*)d_in[1];
    const float* query = (const float*)d_in[2];
    const int*   qmask = (const int*)d_in[3];
    const float* wq    = (const float*)d_in[4];
    const float* wc    = (const float*)d_in[5];
    const float* wqc   = (const float*)d_in[6];
    float* out = (float*)d_out;

    cudaFuncSetAttribute(main_kernel, cudaFuncAttributeMaxDynamicSharedMemorySize, SMEM_BYTES);

    prep_kernel<<<BN*QN, 192>>>(query, wq, wc, wqc);
    qtrans_kernel<<<dim3(24, 4, BN), dim3(32, 8)>>>(query);
    probe_kernel<<<1, 32>>>();                      // main stays launch #4 (ncu slot)
    main_kernel<<<dim3(8, BN), 512, SMEM_BYTES>>>(ctx, cmask, qmask, out);
    q2c_kernel<<<dim3(6, BN, 8), 256>>>(ctx);
    part4_kernel<<<(BN*CN*192)/256, 256>>>(ctx, out);
}

// round 16
// speedup vs baseline: 1.0374x; 1.0374x over previous
#include <cuda_runtime.h>
#include <cuda_bf16.h>
#include <math.h>
#include <stdint.h>

#define BN 32
#define CN 1024
#define QN 128
#define DN 768
#define ODN 3072

// ---------------- smem layout (32-bit word offsets) ---------------------------
// GEMM1: 3 stages x 9216 words [0, 27648): per stage ctx 128x36 + A 128x36
// GEMM2/epilogue (aliased): P bf16 [0,8704), QT bf16 64x68 [8704,13056),
//                           O stage f32 128x68 [17408,26112)
// masks+SRED live in stage-2 footprint, written AFTER GEMM1:
#define P_F     0
#define QTBF_F  8704
#define OST_F   17408
#define SXQ_F   26112
#define SQM_F   26240
#define SCM_F   26368
#define SRED_F  26496   // 512 f
#define SMEM_FLOATS 27648
#define SMEM_BYTES (SMEM_FLOATS*4)

// ---------------- scratch ----------------------------------------------------
__device__ float g_A[(size_t)BN*QN*DN];              // wc + query*wqc
__device__ __nv_bfloat16 g_QTbf[(size_t)BN*DN*QN];   // query^T in bf16 [b][d][q]
__device__ float g_xq[BN*QN];
__device__ float g_m[BN*CN];
__device__ float g_w[BN*CN];
__device__ float g_qp[(size_t)BN*8*DN];              // q2c partials
__device__ float g_q2c[BN*DN];

__device__ __forceinline__ float finf() { return __int_as_float(0x7f800000); }

__device__ __forceinline__ uint32_t s2u(const void* p) {
    uint32_t a;
    asm("{ .reg .u64 t; cvta.to.shared.u64 t, %1; cvt.u32.u64 %0, t; }" : "=r"(a) : "l"(p));
    return a;
}
__device__ __forceinline__ void cpa16(uint32_t dst, const void* src) {
    asm volatile("cp.async.cg.shared.global [%0], [%1], 16;" :: "r"(dst), "l"(src));
}
#define CP_COMMIT() asm volatile("cp.async.commit_group;" ::: "memory")
#define CP_WAIT0()  asm volatile("cp.async.wait_group 0;" ::: "memory")
#define CP_WAIT1()  asm volatile("cp.async.wait_group 1;" ::: "memory")

// m16n8k8 tf32 mma, D += A*B (fp32 accum). Raw fp32 bits as tf32 operands.
__device__ __forceinline__ void mma8(float* d, const uint32_t* a, const uint32_t* b) {
    asm volatile("mma.sync.aligned.m16n8k8.row.col.f32.tf32.tf32.f32 "
        "{%0,%1,%2,%3}, {%4,%5,%6,%7}, {%8,%9}, {%0,%1,%2,%3};"
        : "+f"(d[0]), "+f"(d[1]), "+f"(d[2]), "+f"(d[3])
        : "r"(a[0]), "r"(a[1]), "r"(a[2]), "r"(a[3]), "r"(b[0]), "r"(b[1]));
}
// m16n8k16 bf16 mma, D += A*B (fp32 accum).
__device__ __forceinline__ void mma16(float* d, const uint32_t* a, const uint32_t* b) {
    asm volatile("mma.sync.aligned.m16n8k16.row.col.f32.bf16.bf16.f32 "
        "{%0,%1,%2,%3}, {%4,%5,%6,%7}, {%8,%9}, {%0,%1,%2,%3};"
        : "+f"(d[0]), "+f"(d[1]), "+f"(d[2]), "+f"(d[3])
        : "r"(a[0]), "r"(a[1]), "r"(a[2]), "r"(a[3]), "r"(b[0]), "r"(b[1]));
}
#define LDSM4(d0,d1,d2,d3,a) \
    asm volatile("ldmatrix.sync.aligned.m8n8.x4.shared.b16 {%0,%1,%2,%3}, [%4];" \
        : "=r"(d0), "=r"(d1), "=r"(d2), "=r"(d3) : "r"(a))

// ---------------- kernel 1: A = wc + query*wqc ; xq = query . wq -------------
__global__ void prep_kernel(const float* __restrict__ query,
                            const float* __restrict__ wq,
                            const float* __restrict__ wc,
                            const float* __restrict__ wqc) {
    int row = blockIdx.x;
    int t = threadIdx.x;           // 0..191
    float4 q4  = reinterpret_cast<const float4*>(query)[(size_t)row*192 + t];
    float4 wq4 = reinterpret_cast<const float4*>(wq)[t];
    float4 wc4 = reinterpret_cast<const float4*>(wc)[t];
    float4 wqc4= reinterpret_cast<const float4*>(wqc)[t];
    float4 a4;
    a4.x = wc4.x + q4.x*wqc4.x;
    a4.y = wc4.y + q4.y*wqc4.y;
    a4.z = wc4.z + q4.z*wqc4.z;
    a4.w = wc4.w + q4.w*wqc4.w;
    reinterpret_cast<float4*>(g_A)[(size_t)row*192 + t] = a4;
    float dot = q4.x*wq4.x + q4.y*wq4.y + q4.z*wq4.z + q4.w*wq4.w;
    #pragma unroll
    for (int o=16;o;o>>=1) dot += __shfl_xor_sync(0xffffffffu, dot, o);
    __shared__ float red[6];
    if ((t&31)==0) red[t>>5]=dot;
    __syncthreads();
    if (t==0) g_xq[row] = red[0]+red[1]+red[2]+red[3]+red[4]+red[5];
}

// ---------------- kernel 1b: QTbf[b][d][q] = bf16(query[b][q][d]) ------------
__global__ void qtrans_kernel(const float* __restrict__ query) {
    __shared__ float tile[32][33];
    int b = blockIdx.z, dt = blockIdx.x, qt = blockIdx.y;
    int tx = threadIdx.x, ty = threadIdx.y;   // (32,8)
    const float* qb = query + (size_t)b*QN*DN;
    #pragma unroll
    for (int i=0;i<32;i+=8)
        tile[ty+i][tx] = qb[(size_t)(qt*32+ty+i)*DN + dt*32+tx];
    __syncthreads();
    __nv_bfloat16* QTb = g_QTbf + (size_t)b*DN*QN;
    #pragma unroll
    for (int i=0;i<32;i+=8)
        QTb[(size_t)(dt*32+ty+i)*QN + qt*32+tx] = __float2bfloat16_rn(tile[tx][ty+i]);
}

// ---------------- probe: keeps main_kernel at launch slot #4 for ncu ---------
__global__ void probe_kernel() {
    if (threadIdx.x == 0 && blockIdx.x == 0) g_qp[0] = 0.f;  // overwritten by q2c later
}

// ---------------- kernel 2: main fused mma.sync kernel -----------------------
// grid (8, 32), 512 threads (16 warps in 4x4). smem 110592 B, 2 CTAs/SM.
__device__ __forceinline__ void load_g1(const float* ctxB, const float* AqB,
                                        uint32_t sb, int kt, int st, int tid) {
    int k0 = kt*32;
    #pragma unroll
    for (int p=0;p<2;p++) {
        int idx = tid + p*512;                 // 0..1023
        int row = idx >> 3, seg = idx & 7;
        uint32_t off = (uint32_t)(st*9216 + row*36 + seg*4)*4;
        cpa16(sb + off, ctxB + (size_t)row*DN + k0 + seg*4);
    }
    #pragma unroll
    for (int p=0;p<2;p++) {
        int idx = tid + p*512;
        int row = idx >> 3, seg = idx & 7;
        uint32_t off = (uint32_t)(st*9216 + 4608 + row*36 + seg*4)*4;
        cpa16(sb + off, AqB + (size_t)row*DN + k0 + seg*4);
    }
}

__global__ __launch_bounds__(512, 2)
void main_kernel(const float* __restrict__ ctx,
                 const int* __restrict__ cmask,
                 const int* __restrict__ qmask,
                 float* __restrict__ out) {
    extern __shared__ float smf[];
    uint32_t* smw = (uint32_t*)smf;
    const uint32_t sb = s2u(smf);
    const int tid = threadIdx.x;
    const int wid = tid >> 5, lane = tid & 31;
    const int g = lane >> 2, t = lane & 3;
    const int wm = wid >> 2, wn = wid & 3;   // 4 x 4 warp grid
    const int b = blockIdx.y;
    const int cbase = blockIdx.x << 7;
    const float* ctxB = ctx + ((size_t)(b*CN + cbase))*DN;
    const float* AqB  = g_A + (size_t)b*QN*DN;
    const __nv_bfloat16* QTb = g_QTbf + (size_t)b*DN*QN;

    const int rr = lane & 7, sel = lane >> 3;

    float acc[2][4][4];
    #pragma unroll
    for (int mt=0;mt<2;mt++)
      #pragma unroll
      for (int nt=0;nt<4;nt++)
        #pragma unroll
        for (int r=0;r<4;r++) acc[mt][nt][r]=0.f;

    // GEMM1 ldmatrix base offsets (bytes, relative to stage base).
    // tf32-as-b16 trick: one 8x8 b16 tile == 8 rows x 4 tf32 cols; lane l
    // receives (row l>>2, word l&3) == the (g,t) tf32 fragment mapping.
    uint32_t aOff[2], bOff[2];
    #pragma unroll
    for (int mt=0;mt<2;mt++)
        aOff[mt] = (uint32_t)(((wm*32 + mt*16 + (sel&1)*8 + rr)*36 + (sel>>1)*4)*4);
    #pragma unroll
    for (int j=0;j<2;j++)
        bOff[j]  = (uint32_t)((4608 + (wn*32 + j*16 + (sel&1)*8 + rr)*36 + (sel>>1)*4)*4);

    // -------- GEMM1: S = ctx @ A^T, tf32, 24 K-chunks of 32, 3 stages --------
    load_g1(ctxB, AqB, sb, 0, 0, tid); CP_COMMIT();
    load_g1(ctxB, AqB, sb, 1, 1, tid); CP_COMMIT();
    for (int kt = 0; kt < 24; kt++) {
        CP_WAIT1();                       // stage kt data arrived
        __syncthreads();                  // stage (kt+2)%3 readers (iter kt-1) done
        if (kt + 2 < 24) load_g1(ctxB, AqB, sb, kt+2, (kt+2)%3, tid);
        CP_COMMIT();
        const uint32_t stb = sb + (uint32_t)((kt%3)*9216)*4;
        #pragma unroll
        for (int k8=0;k8<4;k8++) {
            uint32_t a[2][4], bb[4][2];
            LDSM4(a[0][0], a[0][1], a[0][2], a[0][3], stb + aOff[0] + k8*32);
            LDSM4(a[1][0], a[1][1], a[1][2], a[1][3], stb + aOff[1] + k8*32);
            LDSM4(bb[0][0], bb[1][0], bb[0][1], bb[1][1], stb + bOff[0] + k8*32);
            LDSM4(bb[2][0], bb[3][0], bb[2][1], bb[3][1], stb + bOff[1] + k8*32);
            #pragma unroll
            for (int mt=0;mt<2;mt++)
              #pragma unroll
              for (int nt=0;nt<4;nt++)
                mma8(acc[mt][nt], a[mt], bb[nt]);
        }
    }
    __syncthreads();   // all compute done; stage buffers reusable

    // prefetch QT chunk 0 (overlaps the whole softmax epilogue)
    #pragma unroll
    for (int p=0;p<2;p++) {
        int idx = tid + p*512;               // 1024 chunks: 64 rows x 16
        int r = idx >> 4, c = idx & 15;
        cpa16(sb + (uint32_t)(QTBF_F + r*68 + c*4)*4, QTb + (size_t)r*QN + c*8);
    }
    CP_COMMIT();

    // -------- load masks/xq (into stage-2 footprint) -------------------------
    if (tid < 128) {
        smf[SXQ_F + tid] = g_xq[b*QN + tid];
        smf[SQM_F + tid] = (qmask[b*QN + tid] == 1) ? 1.0f : -finf();
        smf[SCM_F + tid] = (cmask[b*CN + cbase + tid] == 1) ? 1.0f : -finf();
    }
    __syncthreads();

    // -------- bias + masks + row softmax over q ------------------------------
    float cm[2][2];
    #pragma unroll
    for (int mt=0;mt<2;mt++) {
        int r0 = wm*32 + mt*16 + g;
        cm[mt][0] = smf[SCM_F + r0];
        cm[mt][1] = smf[SCM_F + r0 + 8];
    }
    float rowmax[2][2];
    #pragma unroll
    for (int mt=0;mt<2;mt++) { rowmax[mt][0] = -finf(); rowmax[mt][1] = -finf(); }
    #pragma unroll
    for (int mt=0;mt<2;mt++)
      #pragma unroll
      for (int nt=0;nt<4;nt++)
        #pragma unroll
        for (int r=0;r<4;r++) {
            int h = r>>1, e = r&1;
            int c0 = wn*32 + nt*8 + 2*t + e;
            float v = (acc[mt][nt][r] + smf[SXQ_F + c0]) * cm[mt][h] * smf[SQM_F + c0];
            if (v == finf()) v = -finf();
            acc[mt][nt][r] = v;
            rowmax[mt][h] = fmaxf(rowmax[mt][h], v);
        }
    #pragma unroll
    for (int mt=0;mt<2;mt++)
      #pragma unroll
      for (int h=0;h<2;h++) {
        float m = rowmax[mt][h];
        m = fmaxf(m, __shfl_xor_sync(0xffffffffu, m, 1));
        m = fmaxf(m, __shfl_xor_sync(0xffffffffu, m, 2));
        if (t == 0) smf[SRED_F + (wm*32 + mt*16 + g + 8*h)*4 + wn] = m;
      }
    __syncthreads();
    float mx[2][2];
    #pragma unroll
    for (int mt=0;mt<2;mt++)
      #pragma unroll
      for (int h=0;h<2;h++) {
        int row = wm*32 + mt*16 + g + 8*h;
        float4 mm = *(const float4*)&smf[SRED_F + row*4];
        float m = fmaxf(fmaxf(mm.x, mm.y), fmaxf(mm.z, mm.w));
        mx[mt][h] = m;
        if (wn == 0 && t == 0) g_m[b*CN + cbase + row] = m;
      }
    float rowsum[2][2];
    #pragma unroll
    for (int mt=0;mt<2;mt++) { rowsum[mt][0] = 0.f; rowsum[mt][1] = 0.f; }
    #pragma unroll
    for (int mt=0;mt<2;mt++)
      #pragma unroll
      for (int nt=0;nt<4;nt++)
        #pragma unroll
        for (int r=0;r<4;r++) {
            int h = r>>1;
            float e = expf(acc[mt][nt][r] - mx[mt][h]);
            acc[mt][nt][r] = e;
            rowsum[mt][h] += e;
        }
    __syncthreads();
    #pragma unroll
    for (int mt=0;mt<2;mt++)
      #pragma unroll
      for (int h=0;h<2;h++) {
        float s = rowsum[mt][h];
        s += __shfl_xor_sync(0xffffffffu, s, 1);
        s += __shfl_xor_sync(0xffffffffu, s, 2);
        if (t == 0) smf[SRED_F + (wm*32 + mt*16 + g + 8*h)*4 + wn] = s;
      }
    __syncthreads();
    // normalize + pack P to bf16x2 words (stride 68, conflict-free)
    #pragma unroll
    for (int mt=0;mt<2;mt++)
      #pragma unroll
      for (int h=0;h<2;h++) {
        int row = wm*32 + mt*16 + g + 8*h;
        float4 ss = *(const float4*)&smf[SRED_F + row*4];
        float inv = 1.0f / (ss.x + ss.y + ss.z + ss.w);
        #pragma unroll
        for (int nt=0;nt<4;nt++) {
            __nv_bfloat162 pv = __floats2bfloat162_rn(acc[mt][nt][h*2+0]*inv,
                                                      acc[mt][nt][h*2+1]*inv);
            smw[P_F + row*68 + wn*16 + nt*4 + t] = *(uint32_t*)&pv;
        }
      }
    __syncthreads();

    // -------- GEMM2: per 64-d chunk O = P @ QT^T (bf16, ldmatrix, pipelined) -
    const uint32_t aB0 = sb + (uint32_t)(P_F + (wm*32 + (sel&1)*8 + rr)*68 + (sel>>1)*4)*4;
    const uint32_t aB1 = aB0 + 16*68*4;
    const uint32_t bB  = sb + (uint32_t)(QTBF_F + (wn*16 + (sel>>1)*8 + rr)*68 + (sel&1)*4)*4;

    for (int dc = 0; dc < 12; dc++) {
        const int dbase = dc*64;
        CP_WAIT0();                       // QT(dc) arrived
        __syncthreads();
        float o2[2][2][4];
        #pragma unroll
        for (int mt=0;mt<2;mt++)
          #pragma unroll
          for (int nt=0;nt<2;nt++)
            #pragma unroll
            for (int r=0;r<4;r++) o2[mt][nt][r]=0.f;
        #pragma unroll
        for (int kk=0;kk<8;kk++) {
            uint32_t a[2][4], bb[2][2];
            LDSM4(a[0][0], a[0][1], a[0][2], a[0][3], aB0 + kk*32);
            LDSM4(a[1][0], a[1][1], a[1][2], a[1][3], aB1 + kk*32);
            LDSM4(bb[0][0], bb[0][1], bb[1][0], bb[1][1], bB + kk*32);
            #pragma unroll
            for (int mt=0;mt<2;mt++)
              #pragma unroll
              for (int nt=0;nt<2;nt++)
                mma16(o2[mt][nt], a[mt], bb[nt]);
        }
        __syncthreads();                  // QT(dc) reads done; buffer reusable
        if (dc < 11) {                    // prefetch QT(dc+1) under staging+stores
            const int dn = (dc+1)*64;
            #pragma unroll
            for (int p=0;p<2;p++) {
                int idx = tid + p*512;
                int r = idx >> 4, c = idx & 15;
                cpa16(sb + (uint32_t)(QTBF_F + r*68 + c*4)*4,
                      QTb + (size_t)(dn + r)*QN + c*8);
            }
            CP_COMMIT();
        }
        // stage O (f32, stride 68), then coalesced float4 stores
        #pragma unroll
        for (int mt=0;mt<2;mt++)
          #pragma unroll
          for (int h=0;h<2;h++) {
            int row = wm*32 + mt*16 + g + 8*h;
            #pragma unroll
            for (int nt=0;nt<2;nt++) {
                float2 ov = make_float2(o2[mt][nt][h*2+0], o2[mt][nt][h*2+1]);
                *(float2*)&smf[OST_F + row*68 + wn*16 + nt*8 + 2*t] = ov;
            }
          }
        __syncthreads();
        #pragma unroll
        for (int p=0;p<4;p++) {
            int row = p*32 + (tid>>4);
            int c4 = (tid&15)*4;
            float4 ov = *(const float4*)&smf[OST_F + row*68 + c4];
            size_t orow = (size_t)(b*CN + cbase + row);
            float4 cv = *(const float4*)(ctx + orow*DN + dbase + c4);
            float* op = out + orow*ODN + dbase + c4;
            __stcs((float4*)(op), cv);
            __stcs((float4*)(op + DN), ov);
            __stcs((float4*)(op + 2*DN),
                   make_float4(cv.x*ov.x, cv.y*ov.y, cv.z*ov.z, cv.w*ov.w));
        }
        __syncthreads();   // OST reads done before next iteration's staging
    }
}

// ---------------- kernel 3: q2c weights = softmax over c of g_m --------------
__global__ void softc_kernel() {
    int b = blockIdx.x, t = threadIdx.x;  // 256 threads
    float v[4]; float mx = -finf();
    #pragma unroll
    for (int i=0;i<4;i++) { v[i] = g_m[b*CN + t + i*256]; mx = fmaxf(mx, v[i]); }
    #pragma unroll
    for (int o=16;o;o>>=1) mx = fmaxf(mx, __shfl_xor_sync(0xffffffffu, mx, o));
    __shared__ float smx[8], ssm[8];
    if ((t&31)==0) smx[t>>5]=mx;
    __syncthreads();
    float bm = smx[0];
    #pragma unroll
    for (int i=1;i<8;i++) bm = fmaxf(bm, smx[i]);
    float s = 0.f;
    #pragma unroll
    for (int i=0;i<4;i++) { float e = expf(v[i]-bm); v[i]=e; s+=e; }
    #pragma unroll
    for (int o=16;o;o>>=1) s += __shfl_xor_sync(0xffffffffu, s, o);
    if ((t&31)==0) ssm[t>>5]=s;
    __syncthreads();
    float tot = ssm[0]+ssm[1]+ssm[2]+ssm[3]+ssm[4]+ssm[5]+ssm[6]+ssm[7];
    float inv = 1.0f / tot;
    #pragma unroll
    for (int i=0;i<4;i++) g_w[b*CN + t + i*256] = v[i]*inv;
}

// ---------------- kernel 4: q2c partials over 128-c chunks -------------------
__global__ void q2c_kernel(const float* __restrict__ ctx) {
    int b = blockIdx.y;
    int dbase = blockIdx.x << 7;
    int cz = blockIdx.z;
    int t = threadIdx.x;
    int col = t & 127;
    int half = t >> 7;
    const float* cp = ctx + ((size_t)(b*CN) + cz*128 + half*64)*DN + dbase + col;
    const float* wp = g_w + b*CN + cz*128 + half*64;
    float a0=0.f,a1=0.f,a2=0.f,a3=0.f;
    for (int c=0;c<64;c+=4) {
        a0 += wp[c+0]*cp[(size_t)(c+0)*DN];
        a1 += wp[c+1]*cp[(size_t)(c+1)*DN];
        a2 += wp[c+2]*cp[(size_t)(c+2)*DN];
        a3 += wp[c+3]*cp[(size_t)(c+3)*DN];
    }
    float acc = (a0+a1)+(a2+a3);
    __shared__ float sred[128];
    if (half) sred[col] = acc;
    __syncthreads();
    if (!half) g_qp[((size_t)b*8 + cz)*DN + dbase + col] = acc + sred[col];
}

// ---------------- kernel 4b: reduce 8 partials -------------------------------
__global__ void q2c_reduce() {
    int i = blockIdx.x*256 + threadIdx.x;   // < BN*DN
    int b = i / DN, d = i - b*DN;
    float s = 0.f;
    #pragma unroll
    for (int z=0;z<8;z++) s += g_qp[((size_t)b*8 + z)*DN + d];
    g_q2c[(size_t)b*DN + d] = s;
}

// ---------------- kernel 5: part4 = ctx * q2c --------------------------------
__global__ void part4_kernel(const float* __restrict__ ctx, float* __restrict__ out) {
    int i4 = blockIdx.x*blockDim.x + threadIdx.x;
    int bc = i4 / 192;
    int d4 = i4 - bc*192;
    float4 cv = reinterpret_cast<const float4*>(ctx)[(size_t)bc*192 + d4];
    float4 qv = reinterpret_cast<const float4*>(g_q2c)[(bc>>10)*192 + d4];
    float4 rr = make_float4(cv.x*qv.x, cv.y*qv.y, cv.z*qv.z, cv.w*qv.w);
    __stcs(&reinterpret_cast<float4*>(out)[(size_t)bc*768 + 576 + d4], rr);
}

// ---------------- launch -----------------------------------------------------
extern "C" void kernel_launch(void* const* d_in, const int* in_sizes, int n_in,
                              void* d_out, int out_size) {
    const float* ctx   = (const float*)d_in[0];
    const int*   cmask = (const int*)d_in[1];
    const float* query = (const float*)d_in[2];
    const int*   qmask = (const int*)d_in[3];
    const float* wq    = (const float*)d_in[4];
    const float* wc    = (const float*)d_in[5];
    const float* wqc   = (const float*)d_in[6];
    float* out = (float*)d_out;

    cudaFuncSetAttribute(main_kernel, cudaFuncAttributeMaxDynamicSharedMemorySize, SMEM_BYTES);

    prep_kernel<<<BN*QN, 192>>>(query, wq, wc, wqc);
    qtrans_kernel<<<dim3(24, 4, BN), dim3(32, 8)>>>(query);
    probe_kernel<<<1, 32>>>();                      // main stays launch #4 (ncu slot)
    main_kernel<<<dim3(8, BN), 512, SMEM_BYTES>>>(ctx, cmask, qmask, out);
    softc_kernel<<<BN, 256>>>();
    q2c_kernel<<<dim3(6, BN, 8), 256>>>(ctx);
    q2c_reduce<<<(BN*DN)/256, 256>>>();
    part4_kernel<<<(BN*CN*192)/256, 256>>>(ctx, out);
}